// round 6
// baseline (speedup 1.0000x reference)
#include <cuda_runtime.h>

// DTCWT 1-D, J=3, fully fused. Phase-1: fully-coalesced float4 loads + warp
// shuffle halo (2 outputs/lane/group). lo1/lo2 in even/odd split smem with
// XOR swizzle (conflict-free for stride 1,2,4 accesses).
// Inputs: 0:x[64,1,2^20] 1:h0o(5) 2:h1o(7) 3:h0a(14) (4,5,6 derived by identity)
// Q-shift identities: h1b[t] = -(-1)^t h0a[t], h1a[t] = (-1)^t h0a[13-t].
// Output (fp32): lo @0, yh0 @8388608, yh1 @41943040, yh2 @75497472

#define N0 (1 << 20)
#define N1 (1 << 19)
#define N2 (1 << 18)
#define N3 (1 << 17)
#define NB 64

#define T3 1024
#define T2 2048
#define T1 4096
#define NT 256

#define OFF_YH0 8388608ull
#define OFF_YH1 41943040ull
#define OFF_YH2 75497472ull

// smem layout (float offsets), all 32-word aligned for the swizzle:
//  LE1[2080]: lo1 at even p1 (idx p1/2, p1 in [0,4136))
//  LO1[2080]: lo1 at odd  p1
//  LE2[1056]: lo2 at even p2 (idx p2/2, p2 in [0,2060))
//  LO2[1056]: lo2 at odd  p2
#define LE1_OFF 0
#define LO1_OFF 2080
#define LE2_OFF 4160
#define LO2_OFF 5216
#define SMEM_FLOATS 6272
#define SMEM_BYTES (SMEM_FLOATS * 4)

__device__ __forceinline__ int SW(int a) { return a ^ ((a >> 5) & 7); }

__global__ __launch_bounds__(NT, 4) void dtcwt_fused_kernel(
    const float* __restrict__ x,
    const float* __restrict__ h0o, const float* __restrict__ h1o,
    const float* __restrict__ h0a,
    float* __restrict__ out)
{
    extern __shared__ float smem[];

    const int tid  = threadIdx.x;
    const int lane = tid & 31;
    const int wrp  = tid >> 5;
    const int blk  = blockIdx.x;     // 0..127
    const int b    = blockIdx.y;     // 0..63

    const float* xb = x + (size_t)b * N0;
    const int i0 = blk * T1;
    const int j0 = blk * T2;

    // ========== Phase 1: level 1, coalesced loads + shuffle halo ==========
    {
        float c0[5], c1[7];
#pragma unroll
        for (int t = 0; t < 5; t++) c0[t] = __ldg(h0o + t);
#pragma unroll
        for (int t = 0; t < 7; t++) c1[t] = __ldg(h1o + t);

        float* yh0p = out + OFF_YH0 + (size_t)b * N1 + i0;
        const long xwb = 2l * i0 + 1024l * wrp;   // warp x base (floats)

#pragma unroll
        for (int g = 0; g < 8; g++) {
            const long G = xwb + 128l * g;        // group x base (512B aligned)
            // own 4 floats: x[G+4l .. G+4l+3]  (always in-bounds)
            const float4 f = *reinterpret_cast<const float4*>(xb + G + 4 * lane);

            // window v[k] = x[G + 4*lane - 3 + k], k = 0..8
            float v0 = __shfl_up_sync(0xffffffffu, f.y, 1);
            float v1 = __shfl_up_sync(0xffffffffu, f.z, 1);
            float v2 = __shfl_up_sync(0xffffffffu, f.w, 1);
            float v7 = __shfl_down_sync(0xffffffffu, f.x, 1);
            float v8 = __shfl_down_sync(0xffffffffu, f.y, 1);
            if (lane == 0) {
                if (G >= 4) {
                    float4 p = *reinterpret_cast<const float4*>(xb + G - 4);
                    v0 = p.y; v1 = p.z; v2 = p.w;
                } else {                          // global left edge: zero-pad
                    v0 = v1 = v2 = 0.0f;
                }
            }
            if (lane == 31) {
                if (G + 128 < N0) {
                    float4 p = *reinterpret_cast<const float4*>(xb + G + 128);
                    v7 = p.x; v8 = p.y;
                } else {                          // global right edge: zero-pad
                    v7 = v8 = 0.0f;
                }
            }

            // outputs i_loc = il, il+1 ; lo[i]=sum h0o[t] x[2i-2+t], hi: x[2i-3+t]
            float lo0 = c0[0]*v1  + c0[1]*v2  + c0[2]*f.x + c0[3]*f.y + c0[4]*f.z;
            float lo1 = c0[0]*f.x + c0[1]*f.y + c0[2]*f.z + c0[3]*f.w + c0[4]*v7;
            float hi0 = c1[0]*v0  + c1[1]*v1  + c1[2]*v2  + c1[3]*f.x
                      + c1[4]*f.y + c1[5]*f.z + c1[6]*f.w;
            float hi1 = c1[0]*v2  + c1[1]*f.x + c1[2]*f.y + c1[3]*f.z
                      + c1[4]*f.w + c1[5]*v7  + c1[6]*v8;

            const int il = 512 * wrp + 64 * g + 2 * lane;
            __stcs(reinterpret_cast<float2*>(yh0p + il), make_float2(hi0, hi1));

            const int m = (il + 20) >> 1;         // p1 = il+20 (even), pair index
            smem[LE1_OFF + SW(m)] = lo0;          // lo1 point p1
            smem[LO1_OFF + SW(m)] = lo1;          // lo1 point p1+1
        }

        // lo1 halo: p1 in [0,20) u [4116,4136)
        if (tid < 40) {
            const int p1 = (tid < 20) ? tid : (4096 + tid);
            const int ig = i0 + p1 - 20;
            float lo = 0.0f;
            if (ig >= 0 && ig < N1) {
#pragma unroll
                for (int t = 0; t < 5; t++) {
                    long g = 2l * ig - 2 + t;
                    float xv = (g >= 0 && g < N0) ? xb[g] : 0.0f;
                    lo = fmaf(c0[t], xv, lo);
                }
            }
            smem[((p1 & 1) ? LO1_OFF : LE1_OFF) + SW(p1 >> 1)] = lo;
        }
    }
    __syncthreads();

    // ========== Phase 2: level 2, 4 outputs/thread x 2 iters ==========
    {
        float a0[14];
#pragma unroll
        for (int t = 0; t < 14; t++) a0[t] = __ldg(h0a + t);

        float* yh1a = out + OFF_YH1 + (size_t)b * (2 * N2);
        float* yh1b = yh1a + N2;

#pragma unroll
        for (int it = 0; it < 2; it++) {
            const int u = tid + it * NT;          // j_loc = 4u..4u+3 (interior)

            // Ev[k]: p1 = 8u+14+2k ; Od[k]: p1 = 8u+15+2k  (k=0..9)
            float Ev[10], Od[10];
#pragma unroll
            for (int k = 0; k < 10; k++) {
                const int a = SW(4 * u + 7 + k);
                Ev[k] = smem[LE1_OFF + a];
                Od[k] = smem[LO1_OFF + a];
            }

            float lov[4], hav[4], hbv[4];
#pragma unroll
            for (int q = 0; q < 4; q++) {
                float pe = 0.f, po = 0.f, hp = 0.f, hm = 0.f;
#pragma unroll
                for (int s = 0; s < 7; s++) {
                    pe = fmaf(a0[2 * s],     Ev[q + s],     pe);
                    po = fmaf(a0[2 * s + 1], Od[q + s],     po);
                    hp = fmaf(a0[2 * s + 1], Ev[q + 6 - s], hp);
                    hm = fmaf(a0[2 * s],     Od[q + 6 - s], hm);
                }
                lov[q] = pe + po;   // h0a
                hbv[q] = po - pe;   // h1b
                hav[q] = hp - hm;   // h1a
            }

            const int jg = j0 + 4 * u;
            __stcs(reinterpret_cast<float4*>(yh1a + jg),
                   make_float4(hav[0], hav[1], hav[2], hav[3]));
            __stcs(reinterpret_cast<float4*>(yh1b + jg),
                   make_float4(hbv[0], hbv[1], hbv[2], hbv[3]));

            // lo2 points p2 = 4u+6+q
            smem[LE2_OFF + SW(2 * u + 3)] = lov[0];
            smem[LO2_OFF + SW(2 * u + 3)] = lov[1];
            smem[LE2_OFF + SW(2 * u + 4)] = lov[2];
            smem[LO2_OFF + SW(2 * u + 4)] = lov[3];
        }

        // lo2 halo: p2 in [0,6) u [2054,2060)
        if (tid < 12) {
            const int p2 = (tid < 6) ? tid : (2048 + tid);
            const int jl = p2 - 6;
            const int jg = j0 + jl;
            float v = 0.0f;
            if (jg >= 0 && jg < N2) {
#pragma unroll
                for (int t = 0; t < 14; t++) {
                    const int p1 = 2 * jl + 14 + t;   // in [2,4133], valid
                    v = fmaf(a0[t],
                             smem[((p1 & 1) ? LO1_OFF : LE1_OFF) + SW(p1 >> 1)],
                             v);
                }
            }
            smem[((p2 & 1) ? LO2_OFF : LE2_OFF) + SW(p2 >> 1)] = v;
        }
    }
    __syncthreads();

    // ========== Phase 3: level 3, 4 outputs/thread ==========
    {
        float a0[14];
#pragma unroll
        for (int t = 0; t < 14; t++) a0[t] = __ldg(h0a + t);

        const int k0 = blk * T3;
        float* lop = out + (size_t)b * N3;
        float* y2a = out + OFF_YH2 + (size_t)b * (2 * N3);
        float* y2b = y2a + N3;

        const int t = tid;                  // k_loc = 4t..4t+3
        // Ev[k]: p2 = 8t+2k ; Od[k]: p2 = 8t+1+2k  (k=0..9)
        float Ev[10], Od[10];
#pragma unroll
        for (int k = 0; k < 10; k++) {
            const int a = SW(4 * t + k);
            Ev[k] = smem[LE2_OFF + a];
            Od[k] = smem[LO2_OFF + a];
        }

        float lov[4], hav[4], hbv[4];
#pragma unroll
        for (int q = 0; q < 4; q++) {
            float pe = 0.f, po = 0.f, hp = 0.f, hm = 0.f;
#pragma unroll
            for (int s = 0; s < 7; s++) {
                pe = fmaf(a0[2 * s],     Ev[q + s],     pe);
                po = fmaf(a0[2 * s + 1], Od[q + s],     po);
                hp = fmaf(a0[2 * s + 1], Ev[q + 6 - s], hp);
                hm = fmaf(a0[2 * s],     Od[q + 6 - s], hm);
            }
            lov[q] = pe + po;
            hbv[q] = po - pe;
            hav[q] = hp - hm;
        }

        const int kg = k0 + 4 * t;
        __stcs(reinterpret_cast<float4*>(lop + kg),
               make_float4(lov[0], lov[1], lov[2], lov[3]));
        __stcs(reinterpret_cast<float4*>(y2a + kg),
               make_float4(hav[0], hav[1], hav[2], hav[3]));
        __stcs(reinterpret_cast<float4*>(y2b + kg),
               make_float4(hbv[0], hbv[1], hbv[2], hbv[3]));
    }
}

extern "C" void kernel_launch(void* const* d_in, const int* in_sizes, int n_in,
                              void* d_out, int out_size)
{
    const float* x   = (const float*)d_in[0];
    const float* h0o = (const float*)d_in[1];
    const float* h1o = (const float*)d_in[2];
    const float* h0a = (const float*)d_in[3];
    float* out = (float*)d_out;

    cudaFuncSetAttribute(dtcwt_fused_kernel,
                         cudaFuncAttributeMaxDynamicSharedMemorySize, SMEM_BYTES);

    dim3 grid(N3 / T3, NB, 1);   // (128, 64)
    dtcwt_fused_kernel<<<grid, NT, SMEM_BYTES>>>(x, h0o, h1o, h0a, out);
}

// round 7
// speedup vs baseline: 1.0080x; 1.0080x over previous
#include <cuda_runtime.h>

// DTCWT 1-D, J=3, fully fused. R5 compute structure; x staged through smem
// with coalesced LDG.128 + XOR-swizzled float4 chunks (conflict-free LDS.128).
// Inputs: 0:x[64,1,2^20] 1:h0o(5) 2:h1o(7) 3:h0a(14) (4,5,6 derived by identity)
// Q-shift identities: h1b[t] = -(-1)^t h0a[t], h1a[t] = (-1)^t h0a[13-t].
// Output (fp32): lo @0, yh0 @8388608, yh1 @41943040, yh2 @75497472

#define N0 (1 << 20)
#define N1 (1 << 19)
#define N2 (1 << 18)
#define N3 (1 << 17)
#define NB 64

#define T3 1024
#define T2 2048
#define T1 4096
#define T0 8192
#define NT 256

// x tile: p in [0, 8280), global g = blk*T0 - 44 + p. Stored as 2070 float4
// chunks, swizzled c ^= (c>>3)&7 (needs 2072 chunks of room).
#define PX4   2070
#define XCH   2072
// lo1 points: p1 in [0, 4136), p1 = i_loc + 20. 8 residue subarrays.
#define L1S  520
// lo2 points: p2 in [0, 2060), p2 = j_loc + 6. 8 residue subarrays (aliases X).
#define L2S  260

#define X_OFF  0
#define L1_OFF (4 * XCH)                 // float offset 8288
#define SMEM_FLOATS (4 * XCH + 8 * L1S)  // 12448 floats = 49792 B
#define SMEM_BYTES  (SMEM_FLOATS * 4)

#define OFF_YH0 8388608ull
#define OFF_YH1 41943040ull
#define OFF_YH2 75497472ull

__device__ __forceinline__ int CSW(int c) { return c ^ ((c >> 3) & 7); }

__global__ __launch_bounds__(NT, 4) void dtcwt_fused_kernel(
    const float* __restrict__ x,
    const float* __restrict__ h0o, const float* __restrict__ h1o,
    const float* __restrict__ h0a,
    float* __restrict__ out)
{
    extern __shared__ float smem[];
    float4* Xc = reinterpret_cast<float4*>(smem);   // swizzled x chunks
    float*  L1 = smem + L1_OFF;                     // 8 * L1S
    float*  L2 = smem;                              // aliases X (dead after ph1)

    const int tid = threadIdx.x;
    const int blk = blockIdx.x;     // 0..127
    const int b   = blockIdx.y;     // 0..63

    const float* xb = x + (size_t)b * N0;
    const int i0 = blk * T1;
    const int j0 = blk * T2;

    // ================= Phase 0: stage x tile (coalesced, swizzled) =========
    {
        const long gb = (long)blk * T0 - 44;
        if (blk != 0 && blk != 127) {
            for (int c = tid; c < PX4; c += NT) {
                float4 f = *reinterpret_cast<const float4*>(xb + gb + 4l * c);
                Xc[CSW(c)] = f;
            }
        } else {
            for (int c = tid; c < PX4; c += NT) {
                long g0 = gb + 4l * c;
                float4 f;
                if (g0 >= 0 && g0 + 4 <= N0) {
                    f = *reinterpret_cast<const float4*>(xb + g0);
                } else {
                    f.x = (g0 >= 0     && g0     < N0) ? xb[g0]     : 0.0f;
                    f.y = (g0 + 1 >= 0 && g0 + 1 < N0) ? xb[g0 + 1] : 0.0f;
                    f.z = (g0 + 2 >= 0 && g0 + 2 < N0) ? xb[g0 + 2] : 0.0f;
                    f.w = (g0 + 3 >= 0 && g0 + 3 < N0) ? xb[g0 + 3] : 0.0f;
                }
                Xc[CSW(c)] = f;
            }
        }
    }
    __syncthreads();

    // ================= Phase 1: level 1 from smem =================
    {
        float c0[5], c1[7];
#pragma unroll
        for (int t = 0; t < 5; t++) c0[t] = __ldg(h0o + t);
#pragma unroll
        for (int t = 0; t < 7; t++) c1[t] = __ldg(h1o + t);

        float* yh0p = out + OFF_YH0 + (size_t)b * N1;

#pragma unroll
        for (int it = 0; it < 2; it++) {
            const int s = tid + it * NT;      // slot: i_loc = 8s..8s+7
            // w[k] = x[2*(i0+8s) - 4 + k] = smem chunk (4s+10)+k/4
            float w[24];
            const int cb = 4 * s + 10;
#pragma unroll
            for (int k = 0; k < 6; k++) {
                float4 f = Xc[CSW(cb + k)];
                w[4 * k] = f.x; w[4 * k + 1] = f.y;
                w[4 * k + 2] = f.z; w[4 * k + 3] = f.w;
            }

            float lo[8], hi[8];
#pragma unroll
            for (int q = 0; q < 8; q++) {
                // lo[i] = sum_t h0o[t] x[2i-2+t]; hi[i] = sum_t h1o[t] x[2i-3+t]
                lo[q] = c0[0]*w[2*q+2] + c0[1]*w[2*q+3] + c0[2]*w[2*q+4]
                      + c0[3]*w[2*q+5] + c0[4]*w[2*q+6];
                hi[q] = c1[0]*w[2*q+1] + c1[1]*w[2*q+2] + c1[2]*w[2*q+3]
                      + c1[3]*w[2*q+4] + c1[4]*w[2*q+5] + c1[5]*w[2*q+6]
                      + c1[6]*w[2*q+7];
            }

            const int ig0 = i0 + 8 * s;
            __stcs(reinterpret_cast<float4*>(yh0p + ig0),
                   make_float4(hi[0], hi[1], hi[2], hi[3]));
            __stcs(reinterpret_cast<float4*>(yh0p + ig0 + 4),
                   make_float4(hi[4], hi[5], hi[6], hi[7]));

            // lo1 point p1 = 8s + 20 + q ; residue const per q, idx lane-consecutive
#pragma unroll
            for (int q = 0; q < 8; q++) {
                const int p1 = 8 * s + 20 + q;
                L1[(p1 & 7) * L1S + (p1 >> 3)] = lo[q];
            }
        }

        // lo1 halo: p1 in [0,20) u [4116,4136), x taps from smem
        if (tid < 40) {
            const int p1 = (tid < 20) ? tid : (4096 + tid);
            const int ig = i0 + p1 - 20;
            float lo = 0.0f;
            if (ig >= 0 && ig < N1) {
#pragma unroll
                for (int t = 0; t < 5; t++) {
                    const int p = 2 * p1 + 2 + t;        // in [2, 8278)
                    const int ch = p >> 2;
                    const float xv = smem[4 * CSW(ch) + (p & 3)];
                    lo = fmaf(c0[t], xv, lo);
                }
            }
            L1[(p1 & 7) * L1S + (p1 >> 3)] = lo;
        }
    }
    __syncthreads();

    // ================= Phase 2: level 2 =================
    {
        float a0[14];
#pragma unroll
        for (int t = 0; t < 14; t++) a0[t] = __ldg(h0a + t);

        float* yh1a = out + OFF_YH1 + (size_t)b * (2 * N2);
        float* yh1b = yh1a + N2;

#pragma unroll
        for (int it = 0; it < 2; it++) {
            const int u = tid + it * NT;    // j_loc = 4u .. 4u+3 (all interior)

            // Ev[k]: p1 = 8u+14+2k ; Od[k]: p1 = 8u+15+2k  (k = 0..9)
            float Ev[10], Od[10];
#pragma unroll
            for (int k = 0; k < 10; k++) {
                int pe = 8 * u + 14 + 2 * k;
                int po = pe + 1;
                Ev[k] = L1[(pe & 7) * L1S + (pe >> 3)];
                Od[k] = L1[(po & 7) * L1S + (po >> 3)];
            }

            float lov[4], hav[4], hbv[4];
#pragma unroll
            for (int q = 0; q < 4; q++) {
                float pe = 0.f, po = 0.f, hp = 0.f, hm = 0.f;
#pragma unroll
                for (int s = 0; s < 7; s++) {
                    pe = fmaf(a0[2 * s],     Ev[q + s],     pe);
                    po = fmaf(a0[2 * s + 1], Od[q + s],     po);
                    hp = fmaf(a0[2 * s + 1], Ev[q + 6 - s], hp);
                    hm = fmaf(a0[2 * s],     Od[q + 6 - s], hm);
                }
                lov[q] = pe + po;   // h0a
                hbv[q] = po - pe;   // h1b
                hav[q] = hp - hm;   // h1a
            }

            const int jg = j0 + 4 * u;
            __stcs(reinterpret_cast<float4*>(yh1a + jg),
                   make_float4(hav[0], hav[1], hav[2], hav[3]));
            __stcs(reinterpret_cast<float4*>(yh1b + jg),
                   make_float4(hbv[0], hbv[1], hbv[2], hbv[3]));

            // lo2 point p2 = 4u + 6 + q
#pragma unroll
            for (int q = 0; q < 4; q++) {
                const int p2 = 4 * u + 6 + q;
                L2[(p2 & 7) * L2S + (p2 >> 3)] = lov[q];
            }
        }

        // lo2 halo: p2 in [0,6) u [2054,2060)
        if (tid < 12) {
            const int p2 = (tid < 6) ? tid : (2048 + tid);
            const int jl = p2 - 6;
            const int jg = j0 + jl;
            float v = 0.0f;
            if (jg >= 0 && jg < N2) {
#pragma unroll
                for (int t = 0; t < 14; t++) {
                    int p1 = 2 * jl + 14 + t;   // in [2, 4133], always valid
                    v = fmaf(a0[t], L1[(p1 & 7) * L1S + (p1 >> 3)], v);
                }
            }
            L2[(p2 & 7) * L2S + (p2 >> 3)] = v;
        }
    }
    __syncthreads();

    // ================= Phase 3: level 3, 4 outputs/thread =================
    {
        float a0[14];
#pragma unroll
        for (int t = 0; t < 14; t++) a0[t] = __ldg(h0a + t);

        const int k0 = blk * T3;
        float* lop = out + (size_t)b * N3;
        float* y2a = out + OFF_YH2 + (size_t)b * (2 * N3);
        float* y2b = y2a + N3;

        const int t = tid;   // k_loc = 4t .. 4t+3
        // Ev[k]: p2 = 8t+2k ; Od[k]: p2 = 8t+1+2k  (k = 0..9)
        float Ev[10], Od[10];
#pragma unroll
        for (int k = 0; k < 10; k++) {
            int pe = 8 * t + 2 * k;
            int po = pe + 1;
            Ev[k] = L2[(pe & 7) * L2S + (pe >> 3)];
            Od[k] = L2[(po & 7) * L2S + (po >> 3)];
        }

        float lov[4], hav[4], hbv[4];
#pragma unroll
        for (int q = 0; q < 4; q++) {
            float pe = 0.f, po = 0.f, hp = 0.f, hm = 0.f;
#pragma unroll
            for (int s = 0; s < 7; s++) {
                pe = fmaf(a0[2 * s],     Ev[q + s],     pe);
                po = fmaf(a0[2 * s + 1], Od[q + s],     po);
                hp = fmaf(a0[2 * s + 1], Ev[q + 6 - s], hp);
                hm = fmaf(a0[2 * s],     Od[q + 6 - s], hm);
            }
            lov[q] = pe + po;
            hbv[q] = po - pe;
            hav[q] = hp - hm;
        }

        const int kg = k0 + 4 * t;
        __stcs(reinterpret_cast<float4*>(lop + kg),
               make_float4(lov[0], lov[1], lov[2], lov[3]));
        __stcs(reinterpret_cast<float4*>(y2a + kg),
               make_float4(hav[0], hav[1], hav[2], hav[3]));
        __stcs(reinterpret_cast<float4*>(y2b + kg),
               make_float4(hbv[0], hbv[1], hbv[2], hbv[3]));
    }
}

extern "C" void kernel_launch(void* const* d_in, const int* in_sizes, int n_in,
                              void* d_out, int out_size)
{
    const float* x   = (const float*)d_in[0];
    const float* h0o = (const float*)d_in[1];
    const float* h1o = (const float*)d_in[2];
    const float* h0a = (const float*)d_in[3];
    float* out = (float*)d_out;

    cudaFuncSetAttribute(dtcwt_fused_kernel,
                         cudaFuncAttributeMaxDynamicSharedMemorySize, SMEM_BYTES);

    dim3 grid(N3 / T3, NB, 1);   // (128, 64)
    dtcwt_fused_kernel<<<grid, NT, SMEM_BYTES>>>(x, h0o, h1o, h0a, out);
}

// round 8
// speedup vs baseline: 1.4148x; 1.4037x over previous
#include <cuda_runtime.h>

// DTCWT 1-D, J=3, fully fused. == R5 kernel (best: 116us) with occupancy push:
// __launch_bounds__(256,5) + phase-1 restructured for lower register pressure
// (lo stored per-output, hi in two 4-chunks) so the 51-reg cap doesn't spill.
// Inputs: 0:x[64,1,2^20] 1:h0o(5) 2:h1o(7) 3:h0a(14) (4,5,6 derived by identity)
// Q-shift identities: h1b[t] = -(-1)^t h0a[t], h1a[t] = (-1)^t h0a[13-t].
// Output (fp32): lo @0, yh0 @8388608, yh1 @41943040, yh2 @75497472

#define N0 (1 << 20)
#define N1 (1 << 19)
#define N2 (1 << 18)
#define N3 (1 << 17)
#define NB 64

#define T3 1024
#define T2 2048
#define T1 4096
#define NT 256

// lo1 points: p1 in [0, 4136), p1 = i_loc + 20. 8 residue subarrays.
#define L1S  520
// lo2 points: p2 in [0, 2060), p2 = j_loc + 6. 8 residue subarrays.
#define L2S  260

#define OFF_YH0 8388608ull
#define OFF_YH1 41943040ull
#define OFF_YH2 75497472ull

#define SMEM_FLOATS (8 * L1S + 8 * L2S)
#define SMEM_BYTES  (SMEM_FLOATS * 4)

__global__ __launch_bounds__(NT, 5) void dtcwt_fused_kernel(
    const float* __restrict__ x,
    const float* __restrict__ h0o, const float* __restrict__ h1o,
    const float* __restrict__ h0a,
    float* __restrict__ out)
{
    extern __shared__ float smem[];
    float* L1 = smem;               // 8 * L1S
    float* L2 = smem + 8 * L1S;     // 8 * L2S

    const int tid = threadIdx.x;
    const int blk = blockIdx.x;     // 0..127
    const int b   = blockIdx.y;     // 0..63

    const float* xb = x + (size_t)b * N0;
    const int i0 = blk * T1;
    const int j0 = blk * T2;

    // ================= Phase 1: level 1, shuffle-halo x reads =================
    {
        float c0[5], c1[7];
#pragma unroll
        for (int t = 0; t < 5; t++) c0[t] = __ldg(h0o + t);
#pragma unroll
        for (int t = 0; t < 7; t++) c1[t] = __ldg(h1o + t);

        float* yh0p = out + OFF_YH0 + (size_t)b * N1;
        const bool interior = (blk != 0) && (blk != 127);   // warp-uniform
        const int lane = tid & 31;

#pragma unroll
        for (int it = 0; it < 2; it++) {
            const int s = tid + it * NT;             // slot: i_loc = 8s..8s+7
            const long gb = 2l * (i0 + 8l * s) - 4;  // window base, 4-float aligned

            float w[24];                             // w[k] = x[gb + k]
            if (interior) {
                // own 16 floats: 4 aligned float4 loads
                const float4* v = reinterpret_cast<const float4*>(xb + gb);
#pragma unroll
                for (int k = 0; k < 4; k++) {
                    float4 f = v[k];
                    w[4 * k] = f.x; w[4 * k + 1] = f.y;
                    w[4 * k + 2] = f.z; w[4 * k + 3] = f.w;
                }
                // halo w[16..23] = next thread's w[0..7]
#pragma unroll
                for (int k = 0; k < 8; k++)
                    w[16 + k] = __shfl_down_sync(0xffffffffu, w[k], 1);
                if (lane == 31) {
                    float4 f4 = v[4], f5 = v[5];
                    w[16] = f4.x; w[17] = f4.y; w[18] = f4.z; w[19] = f4.w;
                    w[20] = f5.x; w[21] = f5.y; w[22] = f5.z; w[23] = f5.w;
                }
            } else {
#pragma unroll
                for (int k = 0; k < 24; k++) {
                    long g = gb + k;
                    w[k] = (g >= 0 && g < N0) ? xb[g] : 0.0f;
                }
            }

            // lo: compute-and-store one at a time (live lo = 1 reg)
            // lo[i] = sum_t h0o[t] x[2i-2+t] ; p1 = 8s + 20 + q
#pragma unroll
            for (int q = 0; q < 8; q++) {
                const float lo = c0[0]*w[2*q+2] + c0[1]*w[2*q+3] + c0[2]*w[2*q+4]
                               + c0[3]*w[2*q+5] + c0[4]*w[2*q+6];
                const int p1 = 8 * s + 20 + q;
                L1[(p1 & 7) * L1S + (p1 >> 3)] = lo;
            }

            // hi: two 4-output chunks, immediate STG (live hi = 4 regs)
            // hi[i] = sum_t h1o[t] x[2i-3+t]
            const int ig0 = i0 + 8 * s;
#pragma unroll
            for (int c = 0; c < 2; c++) {
                float h[4];
#pragma unroll
                for (int r = 0; r < 4; r++) {
                    const int q = 4 * c + r;
                    h[r] = c1[0]*w[2*q+1] + c1[1]*w[2*q+2] + c1[2]*w[2*q+3]
                         + c1[3]*w[2*q+4] + c1[4]*w[2*q+5] + c1[5]*w[2*q+6]
                         + c1[6]*w[2*q+7];
                }
                __stcs(reinterpret_cast<float4*>(yh0p + ig0 + 4 * c),
                       make_float4(h[0], h[1], h[2], h[3]));
            }
        }

        // lo1 halo: p1 in [0,20) u [4116,4136)
        if (tid < 40) {
            const int p1 = (tid < 20) ? tid : (4096 + tid);
            const int ig = i0 + p1 - 20;
            float lo = 0.0f;
            if (ig >= 0 && ig < N1) {
#pragma unroll
                for (int t = 0; t < 5; t++) {
                    long g = 2l * ig - 2 + t;
                    float xv = (g >= 0 && g < N0) ? xb[g] : 0.0f;
                    lo = fmaf(c0[t], xv, lo);
                }
            }
            L1[(p1 & 7) * L1S + (p1 >> 3)] = lo;
        }
    }
    __syncthreads();

    // ================= Phase 2: level 2 =================
    {
        float a0[14];
#pragma unroll
        for (int t = 0; t < 14; t++) a0[t] = __ldg(h0a + t);

        float* yh1a = out + OFF_YH1 + (size_t)b * (2 * N2);
        float* yh1b = yh1a + N2;

#pragma unroll
        for (int it = 0; it < 2; it++) {
            const int u = tid + it * NT;    // j_loc = 4u .. 4u+3 (all interior)

            // Ev[k]: p1 = 8u+14+2k ; Od[k]: p1 = 8u+15+2k  (k = 0..9)
            float Ev[10], Od[10];
#pragma unroll
            for (int k = 0; k < 10; k++) {
                int pe = 8 * u + 14 + 2 * k;
                int po = pe + 1;
                Ev[k] = L1[(pe & 7) * L1S + (pe >> 3)];
                Od[k] = L1[(po & 7) * L1S + (po >> 3)];
            }

            float lov[4], hav[4], hbv[4];
#pragma unroll
            for (int q = 0; q < 4; q++) {
                float pe = 0.f, po = 0.f, hp = 0.f, hm = 0.f;
#pragma unroll
                for (int s = 0; s < 7; s++) {
                    pe = fmaf(a0[2 * s],     Ev[q + s],     pe);
                    po = fmaf(a0[2 * s + 1], Od[q + s],     po);
                    hp = fmaf(a0[2 * s + 1], Ev[q + 6 - s], hp);
                    hm = fmaf(a0[2 * s],     Od[q + 6 - s], hm);
                }
                lov[q] = pe + po;   // h0a
                hbv[q] = po - pe;   // h1b
                hav[q] = hp - hm;   // h1a
            }

            const int jg = j0 + 4 * u;
            __stcs(reinterpret_cast<float4*>(yh1a + jg),
                   make_float4(hav[0], hav[1], hav[2], hav[3]));
            __stcs(reinterpret_cast<float4*>(yh1b + jg),
                   make_float4(hbv[0], hbv[1], hbv[2], hbv[3]));

            // lo2 point p2 = 4u + 6 + q
#pragma unroll
            for (int q = 0; q < 4; q++) {
                const int p2 = 4 * u + 6 + q;
                L2[(p2 & 7) * L2S + (p2 >> 3)] = lov[q];
            }
        }

        // lo2 halo: p2 in [0,6) u [2054,2060)
        if (tid < 12) {
            const int p2 = (tid < 6) ? tid : (2048 + tid);
            const int jl = p2 - 6;
            const int jg = j0 + jl;
            float v = 0.0f;
            if (jg >= 0 && jg < N2) {
#pragma unroll
                for (int t = 0; t < 14; t++) {
                    int p1 = 2 * jl + 14 + t;   // in [2, 4133], always valid
                    v = fmaf(a0[t], L1[(p1 & 7) * L1S + (p1 >> 3)], v);
                }
            }
            L2[(p2 & 7) * L2S + (p2 >> 3)] = v;
        }
    }
    __syncthreads();

    // ================= Phase 3: level 3, 4 outputs/thread =================
    {
        float a0[14];
#pragma unroll
        for (int t = 0; t < 14; t++) a0[t] = __ldg(h0a + t);

        const int k0 = blk * T3;
        float* lop = out + (size_t)b * N3;
        float* y2a = out + OFF_YH2 + (size_t)b * (2 * N3);
        float* y2b = y2a + N3;

        const int t = tid;   // k_loc = 4t .. 4t+3
        // Ev[k]: p2 = 8t+2k ; Od[k]: p2 = 8t+1+2k  (k = 0..9)
        float Ev[10], Od[10];
#pragma unroll
        for (int k = 0; k < 10; k++) {
            int pe = 8 * t + 2 * k;
            int po = pe + 1;
            Ev[k] = L2[(pe & 7) * L2S + (pe >> 3)];
            Od[k] = L2[(po & 7) * L2S + (po >> 3)];
        }

        float lov[4], hav[4], hbv[4];
#pragma unroll
        for (int q = 0; q < 4; q++) {
            float pe = 0.f, po = 0.f, hp = 0.f, hm = 0.f;
#pragma unroll
            for (int s = 0; s < 7; s++) {
                pe = fmaf(a0[2 * s],     Ev[q + s],     pe);
                po = fmaf(a0[2 * s + 1], Od[q + s],     po);
                hp = fmaf(a0[2 * s + 1], Ev[q + 6 - s], hp);
                hm = fmaf(a0[2 * s],     Od[q + 6 - s], hm);
            }
            lov[q] = pe + po;
            hbv[q] = po - pe;
            hav[q] = hp - hm;
        }

        const int kg = k0 + 4 * t;
        __stcs(reinterpret_cast<float4*>(lop + kg),
               make_float4(lov[0], lov[1], lov[2], lov[3]));
        __stcs(reinterpret_cast<float4*>(y2a + kg),
               make_float4(hav[0], hav[1], hav[2], hav[3]));
        __stcs(reinterpret_cast<float4*>(y2b + kg),
               make_float4(hbv[0], hbv[1], hbv[2], hbv[3]));
    }
}

extern "C" void kernel_launch(void* const* d_in, const int* in_sizes, int n_in,
                              void* d_out, int out_size)
{
    const float* x   = (const float*)d_in[0];
    const float* h0o = (const float*)d_in[1];
    const float* h1o = (const float*)d_in[2];
    const float* h0a = (const float*)d_in[3];
    float* out = (float*)d_out;

    cudaFuncSetAttribute(dtcwt_fused_kernel,
                         cudaFuncAttributeMaxDynamicSharedMemorySize, SMEM_BYTES);

    dim3 grid(N3 / T3, NB, 1);   // (128, 64)
    dtcwt_fused_kernel<<<grid, NT, SMEM_BYTES>>>(x, h0o, h1o, h0a, out);
}